// round 1
// baseline (speedup 1.0000x reference)
#include <cuda_runtime.h>
#include <cuda_bf16.h>
#include <cstdint>

// Problem constants
#define PB 4
#define PS 2048
#define PD 512
#define PH 8
#define HD 64
#define BH (PB*PH)          // 32

// Scratch (device globals; no allocations allowed)
__device__ float g_q[BH * HD * PS];      // [bh][d][s]  (d-major, pre-scaled by normalizer)
__device__ float g_k[BH * HD * PS];      // [bh][d][s]
__device__ float g_v[BH * PS * HD];      // [bh][s][d]
__device__ float g_heads[PB * PS * PD];  // [b][s][h*64+hd]
__device__ float g_norm[PB * PS * PD];   // normalized heads

// ---------------------------------------------------------------------------
// SGEMM: C[M,N] = A[M,K] @ B[K,N], fp32, 128x128x16 tile, 8x8/thread, 256 thr
// MODE 0: plain write to C
// MODE 1: Q projection epilogue -> g_q[bh][d][s], scaled by *normPtr
// MODE 2: KV projection epilogue -> g_k (n<512), g_v (n>=512)
// ---------------------------------------------------------------------------
#define BM 128
#define BN 128
#define BK 16
#define TM 8
#define TN 8

template<int MODE>
__global__ void __launch_bounds__(256)
sgemm_k(const float* __restrict__ A, const float* __restrict__ B,
        float* __restrict__ C, int M, int N, int K,
        const float* __restrict__ normPtr)
{
    __shared__ float As[BK * BM];  // [k][m] transposed
    __shared__ float Bs[BK * BN];  // [k][n]

    const int tid  = threadIdx.x;
    const int brow = blockIdx.y;
    const int bcol = blockIdx.x;
    const int tr = tid >> 4;         // 0..15
    const int tc = tid & 15;         // 0..15
    const int row0 = tr * TM;
    const int col0 = tc * TN;

    float acc[TM][TN];
    #pragma unroll
    for (int i = 0; i < TM; i++)
        #pragma unroll
        for (int j = 0; j < TN; j++) acc[i][j] = 0.f;

    const float* Ab = A + (size_t)brow * BM * K;
    const float* Bb = B + bcol * BN;

    for (int k0 = 0; k0 < K; k0 += BK) {
        // Load A tile (128x16) as 512 float4s, store transposed
        #pragma unroll
        for (int l = 0; l < 2; l++) {
            int idx = tid + l * 256;
            int ar = idx >> 2;
            int ac = (idx & 3) * 4;
            float4 a = *(const float4*)(Ab + (size_t)ar * K + k0 + ac);
            As[(ac + 0) * BM + ar] = a.x;
            As[(ac + 1) * BM + ar] = a.y;
            As[(ac + 2) * BM + ar] = a.z;
            As[(ac + 3) * BM + ar] = a.w;
        }
        // Load B tile (16x128)
        #pragma unroll
        for (int l = 0; l < 2; l++) {
            int idx = tid + l * 256;
            int br = idx >> 5;
            int bc = (idx & 31) * 4;
            *(float4*)(Bs + br * BN + bc) =
                *(const float4*)(Bb + (size_t)(k0 + br) * N + bc);
        }
        __syncthreads();

        #pragma unroll
        for (int kk = 0; kk < BK; kk++) {
            float a[TM], b[TN];
            *(float4*)&a[0] = *(float4*)(As + kk * BM + row0);
            *(float4*)&a[4] = *(float4*)(As + kk * BM + row0 + 4);
            *(float4*)&b[0] = *(float4*)(Bs + kk * BN + col0);
            *(float4*)&b[4] = *(float4*)(Bs + kk * BN + col0 + 4);
            #pragma unroll
            for (int i = 0; i < TM; i++)
                #pragma unroll
                for (int j = 0; j < TN; j++)
                    acc[i][j] += a[i] * b[j];
        }
        __syncthreads();
    }

    float scale = 1.f;
    if (MODE == 1) scale = *normPtr;

    #pragma unroll
    for (int i = 0; i < TM; i++) {
        int m = brow * BM + row0 + i;
        int b = m >> 11;        // /2048
        int s = m & 2047;
        #pragma unroll
        for (int j = 0; j < TN; j++) {
            int n = bcol * BN + col0 + j;
            if (MODE == 0) {
                C[(size_t)m * N + n] = acc[i][j];
            } else if (MODE == 1) {
                int h = n >> 6, d = n & 63;
                g_q[(((size_t)(b * PH + h)) * HD + d) * PS + s] = acc[i][j] * scale;
            } else { // MODE == 2
                if (n < PD) {
                    int h = n >> 6, d = n & 63;
                    g_k[(((size_t)(b * PH + h)) * HD + d) * PS + s] = acc[i][j];
                } else {
                    int n2 = n - PD;
                    int h = n2 >> 6, d = n2 & 63;
                    g_v[(((size_t)(b * PH + h)) * PS + s) * HD + d] = acc[i][j];
                }
            }
        }
    }
}

// ---------------------------------------------------------------------------
// Flash attention (fp32), causal, 64x64 tiles, head_dim=64.
// Q pre-scaled by normalizer. Writes g_heads[b][s][h*64+hd].
// ---------------------------------------------------------------------------
__global__ void __launch_bounds__(256)
flash_k()
{
    __shared__ float Qs[64 * 64];   // [d][r]
    __shared__ float KPs[64 * 64];  // K as [d][c], then reused as P [r][k]
    __shared__ float Vs[64 * 64];   // [k][d]

    const int bh = blockIdx.y;
    const int qt = (int)gridDim.x - 1 - (int)blockIdx.x;  // heavy tiles first
    const int qbase = qt * 64;

    const int tid = threadIdx.x;
    const int ty = tid >> 4, tx = tid & 15;
    const int r0 = ty * 4, c0 = tx * 4;

    const float* qp = g_q + (size_t)bh * HD * PS;
    const float* kp = g_k + (size_t)bh * HD * PS;
    const float* vp = g_v + (size_t)bh * PS * HD;

    // Load Q tile: Qs[d*64+r] = qp[d*PS + qbase + r] (coalesced, conflict-free)
    for (int idx = tid; idx < 4096; idx += 256) {
        int d = idx >> 6, r = idx & 63;
        Qs[idx] = qp[(size_t)d * PS + qbase + r];
    }

    float mi[4], li[4], oacc[4][4];
    #pragma unroll
    for (int i = 0; i < 4; i++) {
        mi[i] = -1e30f; li[i] = 0.f;
        #pragma unroll
        for (int j = 0; j < 4; j++) oacc[i][j] = 0.f;
    }

    for (int jt = 0; jt <= qt; jt++) {
        const int kbase = jt * 64;
        __syncthreads();  // protect KPs/Vs from previous iteration's readers
        for (int idx = tid; idx < 4096; idx += 256) {
            int d = idx >> 6, c = idx & 63;
            KPs[idx] = kp[(size_t)d * PS + kbase + c];
        }
        for (int idx = tid; idx < 4096; idx += 256) {
            Vs[idx] = vp[(size_t)kbase * HD + idx];
        }
        __syncthreads();

        // S = Q K^T (4x4 per thread)
        float s[4][4];
        #pragma unroll
        for (int i = 0; i < 4; i++)
            #pragma unroll
            for (int j = 0; j < 4; j++) s[i][j] = 0.f;

        #pragma unroll 16
        for (int d = 0; d < 64; d++) {
            float4 a = *(float4*)(Qs + d * 64 + r0);
            float4 b = *(float4*)(KPs + d * 64 + c0);
            float av[4] = {a.x, a.y, a.z, a.w};
            float bv[4] = {b.x, b.y, b.z, b.w};
            #pragma unroll
            for (int i = 0; i < 4; i++)
                #pragma unroll
                for (int j = 0; j < 4; j++)
                    s[i][j] += av[i] * bv[j];
        }

        // Causal mask on diagonal tile
        if (jt == qt) {
            #pragma unroll
            for (int i = 0; i < 4; i++)
                #pragma unroll
                for (int j = 0; j < 4; j++)
                    if (c0 + j > r0 + i) s[i][j] = -1e30f;
        }

        // Online softmax (row reductions within 16-lane groups)
        #pragma unroll
        for (int i = 0; i < 4; i++) {
            float mx = fmaxf(fmaxf(s[i][0], s[i][1]), fmaxf(s[i][2], s[i][3]));
            #pragma unroll
            for (int o = 8; o >= 1; o >>= 1)
                mx = fmaxf(mx, __shfl_xor_sync(0xffffffffu, mx, o));
            float mn = fmaxf(mi[i], mx);
            float sum = 0.f;
            #pragma unroll
            for (int j = 0; j < 4; j++) {
                s[i][j] = __expf(s[i][j] - mn);
                sum += s[i][j];
            }
            #pragma unroll
            for (int o = 8; o >= 1; o >>= 1)
                sum += __shfl_xor_sync(0xffffffffu, sum, o);
            float alpha = __expf(mi[i] - mn);
            li[i] = li[i] * alpha + sum;
            mi[i] = mn;
            #pragma unroll
            for (int j = 0; j < 4; j++) oacc[i][j] *= alpha;
        }

        __syncthreads();  // all S-readers done with KPs
        #pragma unroll
        for (int i = 0; i < 4; i++)
            *(float4*)(KPs + (r0 + i) * 64 + c0) =
                make_float4(s[i][0], s[i][1], s[i][2], s[i][3]);
        __syncthreads();

        // O += P @ V
        #pragma unroll 16
        for (int k = 0; k < 64; k++) {
            float4 v = *(float4*)(Vs + k * 64 + c0);
            float vv[4] = {v.x, v.y, v.z, v.w};
            float p0 = KPs[(r0 + 0) * 64 + k];
            float p1 = KPs[(r0 + 1) * 64 + k];
            float p2 = KPs[(r0 + 2) * 64 + k];
            float p3 = KPs[(r0 + 3) * 64 + k];
            #pragma unroll
            for (int j = 0; j < 4; j++) {
                oacc[0][j] += p0 * vv[j];
                oacc[1][j] += p1 * vv[j];
                oacc[2][j] += p2 * vv[j];
                oacc[3][j] += p3 * vv[j];
            }
        }
    }

    // Epilogue: heads[b][qbase+r][h*64 + c]
    const int b = bh >> 3, h = bh & 7;
    #pragma unroll
    for (int i = 0; i < 4; i++) {
        float inv = 1.f / li[i];
        float4 o = make_float4(oacc[i][0] * inv, oacc[i][1] * inv,
                               oacc[i][2] * inv, oacc[i][3] * inv);
        size_t off = ((size_t)b * PS + qbase + r0 + i) * PD + h * HD + c0;
        *(float4*)(g_heads + off) = o;
    }
}

// ---------------------------------------------------------------------------
// Cross-head normalization: per (b,s,hd), mean/std over 8 heads (ddof=0)
// ---------------------------------------------------------------------------
__global__ void __launch_bounds__(256)
norm_k(const float* __restrict__ head_mults)
{
    int i = blockIdx.x * blockDim.x + threadIdx.x;  // over B*S*64
    if (i >= PB * PS * HD) return;
    int hd = i & 63;
    int bs = i >> 6;
    size_t base = (size_t)bs * PD + hd;

    float v[PH];
    float mean = 0.f;
    #pragma unroll
    for (int h = 0; h < PH; h++) {
        v[h] = g_heads[base + h * HD];
        mean += v[h];
    }
    mean *= (1.f / PH);
    float var = 0.f;
    #pragma unroll
    for (int h = 0; h < PH; h++) {
        float d = v[h] - mean;
        var += d * d;
    }
    var *= (1.f / PH);
    float inv = 1.f / (sqrtf(var) + 0.01f);
    #pragma unroll
    for (int h = 0; h < PH; h++) {
        g_norm[base + h * HD] = (v[h] - mean) * inv * head_mults[h];
    }
}

// ---------------------------------------------------------------------------
// kernel_launch
// ---------------------------------------------------------------------------
extern "C" void kernel_launch(void* const* d_in, const int* in_sizes, int n_in,
                              void* d_out, int out_size)
{
    const float* query      = (const float*)d_in[0];  // [4,2048,512]
    const float* value      = (const float*)d_in[1];  // [4,2048,512]
    // d_in[2] = mask: pure causal additive mask, implemented analytically (skipped)
    const float* Wq         = (const float*)d_in[3];  // [512,512]
    const float* Wkv        = (const float*)d_in[4];  // [512,1024]
    const float* Wo         = (const float*)d_in[5];  // [512,512]
    const float* normalizer = (const float*)d_in[6];  // scalar
    const float* head_mults = (const float*)d_in[7];  // [1,1,8,1]
    float* out = (float*)d_out;

    const int M = PB * PS;  // 8192

    // 1. Q projection (scaled by normalizer, permuted to [bh][d][s])
    sgemm_k<1><<<dim3(PD / BN, M / BM), 256>>>(query, Wq, nullptr, M, PD, PD, normalizer);

    // 2. KV projection (permuted to g_k [bh][d][s] and g_v [bh][s][d])
    sgemm_k<2><<<dim3(2 * PD / BN, M / BM), 256>>>(value, Wkv, nullptr, M, 2 * PD, PD, nullptr);

    // 3. Causal flash attention -> g_heads
    flash_k<<<dim3(PS / 64, BH), 256>>>();

    // 4. Cross-head normalization -> g_norm
    norm_k<<<(PB * PS * HD + 255) / 256, 256>>>(head_mults);

    // 5. Output projection -> d_out
    float* gnorm_ptr = nullptr;
    cudaGetSymbolAddress((void**)&gnorm_ptr, g_norm);
    sgemm_k<0><<<dim3(PD / BN, M / BM), 256>>>(gnorm_ptr, Wo, out, M, PD, PD, nullptr);
}

// round 2
// speedup vs baseline: 1.8532x; 1.8532x over previous
#include <cuda_runtime.h>
#include <cuda_bf16.h>
#include <cstdint>

// Problem constants
#define PB 4
#define PS 2048
#define PD 512
#define PH 8
#define HD 64
#define BH (PB*PH)          // 32
#define PM (PB*PS)          // 8192

// Scratch (device globals; no allocations allowed)
__device__ float g_q[BH * PS * HD];      // [bh][s][d]  (pre-scaled by normalizer, tf32-rounded)
__device__ float g_k[BH * PS * HD];      // [bh][s][d]
__device__ float g_v[BH * HD * PS];      // [bh][d][s]
__device__ float g_heads[PB * PS * PD];  // [b][s][h*64+hd]
__device__ float g_norm[PB * PS * PD];   // normalized heads

// ---------------------------------------------------------------------------
// helpers
// ---------------------------------------------------------------------------
__device__ __forceinline__ float f2tf32(float x) {
    uint32_t r;
    asm("cvt.rna.tf32.f32 %0, %1;" : "=r"(r) : "f"(x));
    return __uint_as_float(r);
}

__device__ __forceinline__ void mma_tf32(float c[4], const uint32_t a[4], const uint32_t b[2]) {
    asm volatile(
        "mma.sync.aligned.m16n8k8.row.col.f32.tf32.tf32.f32 "
        "{%0,%1,%2,%3}, {%4,%5,%6,%7}, {%8,%9}, {%0,%1,%2,%3};\n"
        : "+f"(c[0]), "+f"(c[1]), "+f"(c[2]), "+f"(c[3])
        : "r"(a[0]), "r"(a[1]), "r"(a[2]), "r"(a[3]), "r"(b[0]), "r"(b[1]));
}

// ---------------------------------------------------------------------------
// TF32 GEMM: C[M,N] = A[M,K] @ B[K,N]. 128x128x32 tile, 256 thr, 8 warps.
// warp grid 4(m) x 2(n); warp tile 32x64 = 2 x 8 m16n8k8 tiles.
// MODE 0: plain C. MODE 1: Q proj -> g_q (scaled). MODE 2: KV -> g_k/g_v.
// ---------------------------------------------------------------------------
#define GAS 36    // As stride
#define GBS 136   // Bs stride

template<int MODE>
__global__ void __launch_bounds__(256)
gemm_tf32(const float* __restrict__ A, const float* __restrict__ B,
          float* __restrict__ C, int N, int K, const float* __restrict__ normPtr)
{
    __shared__ float As[128 * GAS];   // [m][k], 18KB
    __shared__ float Bs[32 * GBS];    // [k][n], 17.4KB

    const int tid  = threadIdx.x;
    const int warp = tid >> 5, lane = tid & 31;
    const int wm = warp >> 1, wn = warp & 1;
    const int lq = lane >> 2;   // 0..7
    const int lr = lane & 3;    // 0..3

    const float* Ab = A + (size_t)blockIdx.y * 128 * K;
    const float* Bb = B + (size_t)blockIdx.x * 128;

    float acc[2][8][4];
    #pragma unroll
    for (int mi = 0; mi < 2; mi++)
        #pragma unroll
        for (int ni = 0; ni < 8; ni++)
            #pragma unroll
            for (int j = 0; j < 4; j++) acc[mi][ni][j] = 0.f;

    for (int k0 = 0; k0 < K; k0 += 32) {
        // A tile 128x32
        #pragma unroll
        for (int l = 0; l < 4; l++) {
            int i = tid + l * 256;
            int ar = i >> 3, ac = (i & 7) * 4;
            float4 v = *(const float4*)(Ab + (size_t)ar * K + k0 + ac);
            v.x = f2tf32(v.x); v.y = f2tf32(v.y); v.z = f2tf32(v.z); v.w = f2tf32(v.w);
            *(float4*)(As + ar * GAS + ac) = v;
        }
        // B tile 32x128
        #pragma unroll
        for (int l = 0; l < 4; l++) {
            int i = tid + l * 256;
            int br = i >> 5, bc = (i & 31) * 4;
            float4 v = *(const float4*)(Bb + (size_t)(k0 + br) * N + bc);
            v.x = f2tf32(v.x); v.y = f2tf32(v.y); v.z = f2tf32(v.z); v.w = f2tf32(v.w);
            *(float4*)(Bs + br * GBS + bc) = v;
        }
        __syncthreads();

        #pragma unroll
        for (int ks = 0; ks < 4; ks++) {
            const int k = ks * 8;
            uint32_t a[2][4];
            #pragma unroll
            for (int mi = 0; mi < 2; mi++) {
                int base = wm * 32 + mi * 16 + lq;
                a[mi][0] = __float_as_uint(As[base * GAS + k + lr]);
                a[mi][1] = __float_as_uint(As[(base + 8) * GAS + k + lr]);
                a[mi][2] = __float_as_uint(As[base * GAS + k + lr + 4]);
                a[mi][3] = __float_as_uint(As[(base + 8) * GAS + k + lr + 4]);
            }
            #pragma unroll
            for (int ni = 0; ni < 8; ni++) {
                uint32_t b[2];
                int bc = wn * 64 + ni * 8 + lq;
                b[0] = __float_as_uint(Bs[(k + lr) * GBS + bc]);
                b[1] = __float_as_uint(Bs[(k + lr + 4) * GBS + bc]);
                mma_tf32(acc[0][ni], a[0], b);
                mma_tf32(acc[1][ni], a[1], b);
            }
        }
        __syncthreads();
    }

    float scale = 1.f;
    if (MODE == 1) scale = *normPtr;

    #pragma unroll
    for (int mi = 0; mi < 2; mi++) {
        #pragma unroll
        for (int rr = 0; rr < 2; rr++) {
            int m = blockIdx.y * 128 + wm * 32 + mi * 16 + lq + rr * 8;
            int b = m >> 11, s = m & 2047;
            #pragma unroll
            for (int ni = 0; ni < 8; ni++) {
                int c = blockIdx.x * 128 + wn * 64 + ni * 8 + lr * 2;
                float v0 = acc[mi][ni][rr * 2], v1 = acc[mi][ni][rr * 2 + 1];
                if (MODE == 0) {
                    *(float2*)(C + (size_t)m * N + c) = make_float2(v0, v1);
                } else if (MODE == 1) {
                    int h = c >> 6, dd = c & 63;
                    size_t off = (((size_t)(b * PH + h)) * PS + s) * HD + dd;
                    *(float2*)(g_q + off) =
                        make_float2(f2tf32(v0 * scale), f2tf32(v1 * scale));
                } else { // MODE 2
                    if (c < PD) {
                        int h = c >> 6, dd = c & 63;
                        size_t off = (((size_t)(b * PH + h)) * PS + s) * HD + dd;
                        *(float2*)(g_k + off) = make_float2(f2tf32(v0), f2tf32(v1));
                    } else {
                        int c2 = c - PD;
                        int h = c2 >> 6, dd = c2 & 63;
                        size_t off = (((size_t)(b * PH + h)) * HD + dd) * PS + s;
                        g_v[off]      = f2tf32(v0);
                        g_v[off + PS] = f2tf32(v1);
                    }
                }
            }
        }
    }
}

// ---------------------------------------------------------------------------
// TF32 flash attention. 128 q-rows x 64 kv-cols per tile, 8 warps (16 rows ea).
// Q pre-scaled. Causal. smem: Qs[128][68], Ks[64][68], Vs[64][68], Ps[128][68].
// ---------------------------------------------------------------------------
#define FST 68

__global__ void __launch_bounds__(256, 2)
flash_tf32()
{
    extern __shared__ float sm[];
    float* Qs = sm;                 // [r][d]
    float* Ks = sm + 128 * FST;     // [kv][d]
    float* Vs = Ks + 64 * FST;      // [d][kv]
    float* Ps = Vs + 64 * FST;      // [r][kv]

    const int bh = blockIdx.y;
    const int qt = (int)gridDim.x - 1 - (int)blockIdx.x;  // heavy tiles first
    const int qbase = qt * 128;

    const int tid  = threadIdx.x;
    const int warp = tid >> 5, lane = tid & 31;
    const int lq = lane >> 2, lr = lane & 3;
    const int wrow = warp * 16;

    const float* qp = g_q + (size_t)bh * PS * HD;
    const float* kp = g_k + (size_t)bh * PS * HD;
    const float* vp = g_v + (size_t)bh * HD * PS;

    // Load Q tile (already tf32-rounded in projection)
    #pragma unroll
    for (int l = 0; l < 8; l++) {
        int i = tid + l * 256;
        int r = i >> 4, c = (i & 15) * 4;
        *(float4*)(Qs + r * FST + c) = *(const float4*)(qp + (size_t)(qbase + r) * HD + c);
    }

    float mi2[2] = {-1e30f, -1e30f};
    float li2[2] = {0.f, 0.f};
    float o[8][4];
    #pragma unroll
    for (int ni = 0; ni < 8; ni++)
        #pragma unroll
        for (int j = 0; j < 4; j++) o[ni][j] = 0.f;

    const int ktiles = 2 * qt + 2;
    for (int jt = 0; jt < ktiles; jt++) {
        const int kb = jt * 64;
        __syncthreads();
        // Ks[kv][d]
        #pragma unroll
        for (int l = 0; l < 4; l++) {
            int i = tid + l * 256;
            int r = i >> 4, c = (i & 15) * 4;
            *(float4*)(Ks + r * FST + c) = *(const float4*)(kp + (size_t)(kb + r) * HD + c);
        }
        // Vs[d][kv]
        #pragma unroll
        for (int l = 0; l < 4; l++) {
            int i = tid + l * 256;
            int d = i >> 4, c = (i & 15) * 4;
            *(float4*)(Vs + d * FST + c) = *(const float4*)(vp + (size_t)d * PS + kb + c);
        }
        __syncthreads();

        // S = Q K^T
        float s[8][4];
        #pragma unroll
        for (int ni = 0; ni < 8; ni++)
            #pragma unroll
            for (int j = 0; j < 4; j++) s[ni][j] = 0.f;

        const int qr = wrow + lq;
        #pragma unroll
        for (int ks = 0; ks < 8; ks++) {
            const int k = ks * 8;
            uint32_t a[4];
            a[0] = __float_as_uint(Qs[qr * FST + k + lr]);
            a[1] = __float_as_uint(Qs[(qr + 8) * FST + k + lr]);
            a[2] = __float_as_uint(Qs[qr * FST + k + lr + 4]);
            a[3] = __float_as_uint(Qs[(qr + 8) * FST + k + lr + 4]);
            #pragma unroll
            for (int ni = 0; ni < 8; ni++) {
                uint32_t b[2];
                b[0] = __float_as_uint(Ks[(ni * 8 + lq) * FST + k + lr]);
                b[1] = __float_as_uint(Ks[(ni * 8 + lq) * FST + k + lr + 4]);
                mma_tf32(s[ni], a, b);
            }
        }

        // Causal mask (skip if tile entirely below diagonal for this warp)
        if (kb + 63 > qbase + wrow) {
            #pragma unroll
            for (int ni = 0; ni < 8; ni++)
                #pragma unroll
                for (int j = 0; j < 4; j++) {
                    int col = kb + ni * 8 + lr * 2 + (j & 1);
                    int row = qbase + wrow + lq + ((j >> 1) << 3);
                    if (col > row) s[ni][j] = -1e30f;
                }
        }

        // Online softmax (2 rows/thread, quad reduction over lr)
        #pragma unroll
        for (int rr = 0; rr < 2; rr++) {
            float mx = -1e30f;
            #pragma unroll
            for (int ni = 0; ni < 8; ni++)
                mx = fmaxf(mx, fmaxf(s[ni][rr * 2], s[ni][rr * 2 + 1]));
            mx = fmaxf(mx, __shfl_xor_sync(0xffffffffu, mx, 1));
            mx = fmaxf(mx, __shfl_xor_sync(0xffffffffu, mx, 2));
            float mn = fmaxf(mi2[rr], mx);
            float alpha = __expf(mi2[rr] - mn);
            float sum = 0.f;
            #pragma unroll
            for (int ni = 0; ni < 8; ni++) {
                s[ni][rr * 2]     = __expf(s[ni][rr * 2]     - mn);
                s[ni][rr * 2 + 1] = __expf(s[ni][rr * 2 + 1] - mn);
                sum += s[ni][rr * 2] + s[ni][rr * 2 + 1];
            }
            sum += __shfl_xor_sync(0xffffffffu, sum, 1);
            sum += __shfl_xor_sync(0xffffffffu, sum, 2);
            li2[rr] = li2[rr] * alpha + sum;
            mi2[rr] = mn;
            #pragma unroll
            for (int ni = 0; ni < 8; ni++) {
                o[ni][rr * 2]     *= alpha;
                o[ni][rr * 2 + 1] *= alpha;
            }
        }

        // Store P to Ps (per-warp rows only)
        #pragma unroll
        for (int rr = 0; rr < 2; rr++) {
            int r = wrow + lq + rr * 8;
            #pragma unroll
            for (int ni = 0; ni < 8; ni++) {
                *(float2*)(Ps + r * FST + ni * 8 + lr * 2) =
                    make_float2(f2tf32(s[ni][rr * 2]), f2tf32(s[ni][rr * 2 + 1]));
            }
        }
        __syncwarp();

        // O += P V
        #pragma unroll
        for (int ks = 0; ks < 8; ks++) {
            const int k = ks * 8;
            uint32_t a[4];
            a[0] = __float_as_uint(Ps[qr * FST + k + lr]);
            a[1] = __float_as_uint(Ps[(qr + 8) * FST + k + lr]);
            a[2] = __float_as_uint(Ps[qr * FST + k + lr + 4]);
            a[3] = __float_as_uint(Ps[(qr + 8) * FST + k + lr + 4]);
            #pragma unroll
            for (int ni = 0; ni < 8; ni++) {
                uint32_t b[2];
                b[0] = __float_as_uint(Vs[(ni * 8 + lq) * FST + k + lr]);
                b[1] = __float_as_uint(Vs[(ni * 8 + lq) * FST + k + lr + 4]);
                mma_tf32(o[ni], a, b);
            }
        }
    }

    // Epilogue: heads[b][row][h*64 + d]
    const int b = bh >> 3, h = bh & 7;
    #pragma unroll
    for (int rr = 0; rr < 2; rr++) {
        float inv = 1.f / li2[rr];
        int row = qbase + wrow + lq + rr * 8;
        #pragma unroll
        for (int ni = 0; ni < 8; ni++) {
            size_t off = ((size_t)b * PS + row) * PD + h * HD + ni * 8 + lr * 2;
            *(float2*)(g_heads + off) =
                make_float2(o[ni][rr * 2] * inv, o[ni][rr * 2 + 1] * inv);
        }
    }
}

// ---------------------------------------------------------------------------
// Cross-head normalization: per (b,s,hd), mean/std over 8 heads (ddof=0)
// ---------------------------------------------------------------------------
__global__ void __launch_bounds__(256)
norm_k(const float* __restrict__ head_mults)
{
    int i = blockIdx.x * blockDim.x + threadIdx.x;  // over B*S*64
    if (i >= PB * PS * HD) return;
    int hd = i & 63;
    int bs = i >> 6;
    size_t base = (size_t)bs * PD + hd;

    float v[PH];
    float mean = 0.f;
    #pragma unroll
    for (int h = 0; h < PH; h++) {
        v[h] = g_heads[base + h * HD];
        mean += v[h];
    }
    mean *= (1.f / PH);
    float var = 0.f;
    #pragma unroll
    for (int h = 0; h < PH; h++) {
        float d = v[h] - mean;
        var += d * d;
    }
    var *= (1.f / PH);
    float inv = 1.f / (sqrtf(var) + 0.01f);
    #pragma unroll
    for (int h = 0; h < PH; h++) {
        g_norm[base + h * HD] = (v[h] - mean) * inv * head_mults[h];
    }
}

// ---------------------------------------------------------------------------
// kernel_launch
// ---------------------------------------------------------------------------
extern "C" void kernel_launch(void* const* d_in, const int* in_sizes, int n_in,
                              void* d_out, int out_size)
{
    const float* query      = (const float*)d_in[0];  // [4,2048,512]
    const float* value      = (const float*)d_in[1];  // [4,2048,512]
    // d_in[2] = mask: pure causal additive mask, implemented analytically
    const float* Wq         = (const float*)d_in[3];  // [512,512]
    const float* Wkv        = (const float*)d_in[4];  // [512,1024]
    const float* Wo         = (const float*)d_in[5];  // [512,512]
    const float* normalizer = (const float*)d_in[6];  // scalar
    const float* head_mults = (const float*)d_in[7];  // [1,1,8,1]
    float* out = (float*)d_out;

    static bool attr_set = false;
    if (!attr_set) {
        cudaFuncSetAttribute(flash_tf32,
                             cudaFuncAttributeMaxDynamicSharedMemorySize,
                             (128 + 64 + 64 + 128) * FST * 4);
        attr_set = true;
    }

    // 1. Q projection (scaled, -> g_q [bh][s][d])
    gemm_tf32<1><<<dim3(PD / 128, PM / 128), 256>>>(query, Wq, nullptr, PD, PD, normalizer);

    // 2. KV projection (-> g_k [bh][s][d], g_v [bh][d][s])
    gemm_tf32<2><<<dim3(2 * PD / 128, PM / 128), 256>>>(value, Wkv, nullptr, 2 * PD, PD, nullptr);

    // 3. Causal flash attention -> g_heads
    flash_tf32<<<dim3(PS / 128, BH), 256, (128 + 64 + 64 + 128) * FST * 4>>>();

    // 4. Cross-head normalization -> g_norm
    norm_k<<<(PB * PS * HD + 255) / 256, 256>>>(head_mults);

    // 5. Output projection -> d_out
    float* gnorm_ptr = nullptr;
    cudaGetSymbolAddress((void**)&gnorm_ptr, g_norm);
    gemm_tf32<0><<<dim3(PD / 128, PM / 128), 256>>>(gnorm_ptr, Wo, out, PD, PD, nullptr);
}

// round 4
// speedup vs baseline: 5.5139x; 2.9754x over previous
#include <cuda_runtime.h>
#include <cuda_fp16.h>
#include <cstdint>

// Problem constants
#define PB 4
#define PS 2048
#define PD 512
#define PH 8
#define HD 64
#define BH (PB*PH)          // 32
#define PM (PB*PS)          // 8192

// Scratch (device globals; no allocations allowed)
__device__ __half g_qin[PM * PD];        // query in fp16
__device__ __half g_vin[PM * PD];        // value in fp16
__device__ __half g_wT[3 * PD * PD];     // [Wq^T | Wk^T | Wv^T] fp16, [n][k]
__device__ __half g_woT[PD * PD];        // Wo^T fp16 [n][k]
__device__ __half g_q[BH * PS * HD];     // [bh][s][d] fp16, pre-scaled by normalizer
__device__ __half g_k[BH * PS * HD];     // [bh][s][d] fp16
__device__ __half g_v[BH * PS * HD];     // [bh][s][d] fp16
__device__ float  g_heads[PB * PS * PD]; // [b][s][h*64+hd] fp32
__device__ __half g_normh[PM * PD];      // normalized heads fp16

// ---------------------------------------------------------------------------
// helpers
// ---------------------------------------------------------------------------
__device__ __forceinline__ uint32_t smem_u32(const void* p) {
    uint32_t a;
    asm("{ .reg .u64 t; cvta.to.shared.u64 t, %1; cvt.u32.u64 %0, t; }"
        : "=r"(a) : "l"(p));
    return a;
}

#define SW128(off) ((off) ^ (((off) >> 3) & 0x70))

#define CP16(dst, src) \
    asm volatile("cp.async.cg.shared.global [%0], [%1], 16;" \
                 :: "r"((uint32_t)(dst)), "l"(src))
#define CP_COMMIT() asm volatile("cp.async.commit_group;" ::: "memory")
#define CP_WAIT(n)  asm volatile("cp.async.wait_group %0;" :: "n"(n) : "memory")

#define LDSM_X4(r0, r1, r2, r3, addr) \
    asm volatile("ldmatrix.sync.aligned.m8n8.x4.shared.b16 {%0,%1,%2,%3}, [%4];" \
                 : "=r"(r0), "=r"(r1), "=r"(r2), "=r"(r3) : "r"(addr))
#define LDSM_X4_T(r0, r1, r2, r3, addr) \
    asm volatile("ldmatrix.sync.aligned.m8n8.x4.trans.shared.b16 {%0,%1,%2,%3}, [%4];" \
                 : "=r"(r0), "=r"(r1), "=r"(r2), "=r"(r3) : "r"(addr))

__device__ __forceinline__ void mma_f16(float c[4], uint32_t a0, uint32_t a1,
                                        uint32_t a2, uint32_t a3,
                                        uint32_t b0, uint32_t b1) {
    asm volatile(
        "mma.sync.aligned.m16n8k16.row.col.f32.f16.f16.f32 "
        "{%0,%1,%2,%3}, {%4,%5,%6,%7}, {%8,%9}, {%0,%1,%2,%3};\n"
        : "+f"(c[0]), "+f"(c[1]), "+f"(c[2]), "+f"(c[3])
        : "r"(a0), "r"(a1), "r"(a2), "r"(a3), "r"(b0), "r"(b1));
}

// ---------------------------------------------------------------------------
// fp32 -> fp16 bulk convert (vectorized)
// ---------------------------------------------------------------------------
__global__ void __launch_bounds__(256)
a2h(const float* __restrict__ in, __half* __restrict__ out)
{
    int i = (blockIdx.x * 256 + threadIdx.x) * 4;
    float4 v = *(const float4*)(in + i);
    __half2 h0 = __floats2half2_rn(v.x, v.y);
    __half2 h1 = __floats2half2_rn(v.z, v.w);
    *(uint2*)(out + i) = make_uint2(*(uint32_t*)&h0, *(uint32_t*)&h1);
}

// ---------------------------------------------------------------------------
// Weight transpose + fp16 convert: out[n][k] = h(in[k][n]); in [Kd][Nd]
// ---------------------------------------------------------------------------
__global__ void __launch_bounds__(256)
wtrans(const float* __restrict__ in, __half* __restrict__ out, int Kd, int Nd)
{
    __shared__ float t[32][33];
    int bn = blockIdx.x * 32, bk = blockIdx.y * 32;
    int tx = threadIdx.x & 31, ty = threadIdx.x >> 5;
    #pragma unroll
    for (int j = 0; j < 32; j += 8)
        t[ty + j][tx] = in[(size_t)(bk + ty + j) * Nd + bn + tx];
    __syncthreads();
    #pragma unroll
    for (int j = 0; j < 32; j += 8)
        out[(size_t)(bn + ty + j) * Kd + bk + tx] = __float2half(t[tx][ty + j]);
}

// ---------------------------------------------------------------------------
// fp16 GEMM core: 128x128 CTA tile, K=512 in 8 chunks of 64, cp.async
// double-buffered, ldmatrix fragments, m16n8k16 f32-accumulate.
// MODE 0: fused QKV projection (bx: 0-3 Q, 4-7 K, 8-11 V)
// MODE 1: output projection -> fp32 C
// ---------------------------------------------------------------------------
template<int MODE>
__global__ void __launch_bounds__(256, 2)
gemm_h(const __half* __restrict__ Aq, const __half* __restrict__ Av,
       const __half* __restrict__ W, float* __restrict__ C,
       const float* __restrict__ normPtr)
{
    extern __shared__ char dsm[];
    uint32_t raw = smem_u32(dsm);
    uint32_t sb = (raw + 1023u) & ~1023u;

    const int tid = threadIdx.x, warp = tid >> 5, lane = tid & 31;
    const int wm = warp & 3, wn = warp >> 2;
    const int lq = lane >> 2, lr = lane & 3;
    const int bx = blockIdx.x;
    const int m0 = blockIdx.y * 128;
    const int n0 = bx * 128;
    const int sector = (MODE == 0) ? (bx >> 2) : 0;

    const __half* A = (MODE == 0) ? ((sector == 0) ? Aq : Av) : Aq;

    float acc[2][8][4];
    #pragma unroll
    for (int mi = 0; mi < 2; mi++)
        #pragma unroll
        for (int ni = 0; ni < 8; ni++)
            #pragma unroll
            for (int j = 0; j < 4; j++) acc[mi][ni][j] = 0.f;

    // chunk loader: A 128x64h + B 128x64h into buffer (i&1)
    auto load_chunk = [&](int i) {
        const int k0 = i * 64;
        const uint32_t dA = sb + (i & 1) * 32768;
        const uint32_t dB = dA + 16384;
        #pragma unroll
        for (int l = 0; l < 4; l++) {
            int idx = tid + l * 256;
            int r = idx >> 3, c = (idx & 7) * 8;
            CP16(dA + SW128(r * 128 + c * 2), A + (size_t)(m0 + r) * PD + k0 + c);
            CP16(dB + SW128(r * 128 + c * 2), W + (size_t)(n0 + r) * PD + k0 + c);
        }
        CP_COMMIT();
    };

    load_chunk(0);

    #pragma unroll 1
    for (int i = 0; i < 8; i++) {
        if (i + 1 < 8) { load_chunk(i + 1); CP_WAIT(1); }
        else           { CP_WAIT(0); }
        __syncthreads();

        const uint32_t Ab = sb + (i & 1) * 32768;
        const uint32_t Bb = Ab + 16384;
        #pragma unroll
        for (int ks = 0; ks < 4; ks++) {
            const int kh = ks * 16 + (lane >> 4) * 8;
            uint32_t a[2][4];
            #pragma unroll
            for (int mi = 0; mi < 2; mi++) {
                int row = wm * 32 + mi * 16 + (lane & 15);
                LDSM_X4(a[mi][0], a[mi][1], a[mi][2], a[mi][3],
                        Ab + SW128(row * 128 + kh * 2));
            }
            #pragma unroll
            for (int np = 0; np < 4; np++) {
                uint32_t r0, r1, r2, r3;
                int row = wn * 64 + np * 16 + (lane & 15);
                LDSM_X4(r0, r1, r2, r3, Bb + SW128(row * 128 + kh * 2));
                #pragma unroll
                for (int mi = 0; mi < 2; mi++) {
                    mma_f16(acc[mi][2 * np],     a[mi][0], a[mi][1], a[mi][2], a[mi][3], r0, r2);
                    mma_f16(acc[mi][2 * np + 1], a[mi][0], a[mi][1], a[mi][2], a[mi][3], r1, r3);
                }
            }
        }
        __syncthreads();
    }

    // Epilogue
    if (MODE == 1) {
        #pragma unroll
        for (int mi = 0; mi < 2; mi++)
            #pragma unroll
            for (int rr = 0; rr < 2; rr++) {
                int m = m0 + wm * 32 + mi * 16 + lq + rr * 8;
                #pragma unroll
                for (int ni = 0; ni < 8; ni++) {
                    int c = n0 + wn * 64 + ni * 8 + 2 * lr;
                    *(float2*)(C + (size_t)m * PD + c) =
                        make_float2(acc[mi][ni][rr * 2], acc[mi][ni][rr * 2 + 1]);
                }
            }
    } else {
        const float scale = (sector == 0) ? *normPtr : 1.f;
        __half* dst = (sector == 0) ? g_q : ((sector == 1) ? g_k : g_v);
        #pragma unroll
        for (int mi = 0; mi < 2; mi++)
            #pragma unroll
            for (int rr = 0; rr < 2; rr++) {
                int m = m0 + wm * 32 + mi * 16 + lq + rr * 8;
                int b = m >> 11, s = m & 2047;
                #pragma unroll
                for (int ni = 0; ni < 8; ni++) {
                    int nn = (bx & 3) * 128 + wn * 64 + ni * 8 + 2 * lr;
                    int h = nn >> 6, d = nn & 63;
                    __half2 hv = __floats2half2_rn(acc[mi][ni][rr * 2] * scale,
                                                   acc[mi][ni][rr * 2 + 1] * scale);
                    *(__half2*)(dst + (((size_t)(b * PH + h)) * PS + s) * HD + d) = hv;
                }
            }
    }
}

// ---------------------------------------------------------------------------
// fp16 flash attention: 128 q-rows x 64 kv per step, 8 warps (16 rows each),
// cp.async double-buffered K/V, ldmatrix frags, V transposed via ldmatrix.trans.
// Causal; Q pre-scaled. Output g_heads fp32.
// ---------------------------------------------------------------------------
__global__ void __launch_bounds__(256, 2)
flash_h()
{
    extern __shared__ char dsm[];
    uint32_t raw = smem_u32(dsm);
    uint32_t sb = (raw + 1023u) & ~1023u;
    const uint32_t Qs = sb;            // 16KB  [r][d]
    const uint32_t Ps = sb + 16384;    // 16KB  [r][kv]
    // KV buffers: buf b: K at sb+32768+b*16384, V at +8192

    const int bh = blockIdx.y;
    const int qt = (int)gridDim.x - 1 - (int)blockIdx.x;  // heavy first
    const int qbase = qt * 128;

    const int tid = threadIdx.x, warp = tid >> 5, lane = tid & 31;
    const int lq = lane >> 2, lr = lane & 3;
    const int wrow = warp * 16;

    const __half* qp = g_q + (size_t)bh * PS * HD;
    const __half* kp = g_k + (size_t)bh * PS * HD;
    const __half* vp = g_v + (size_t)bh * PS * HD;

    auto load_kv = [&](int jt) {
        const int kb = jt * 64;
        const uint32_t Kb = sb + 32768 + (jt & 1) * 16384;
        const uint32_t Vb = Kb + 8192;
        #pragma unroll
        for (int l = 0; l < 2; l++) {
            int idx = tid + l * 256;
            int r = idx >> 3, c = (idx & 7) * 8;
            CP16(Kb + SW128(r * 128 + c * 2), kp + (size_t)(kb + r) * HD + c);
            CP16(Vb + SW128(r * 128 + c * 2), vp + (size_t)(kb + r) * HD + c);
        }
        CP_COMMIT();
    };

    // Q tile
    #pragma unroll
    for (int l = 0; l < 4; l++) {
        int idx = tid + l * 256;
        int r = idx >> 3, c = (idx & 7) * 8;
        CP16(Qs + SW128(r * 128 + c * 2), qp + (size_t)(qbase + r) * HD + c);
    }
    load_kv(0);   // commit groups Q + KV0 together

    float mi2[2] = {-1e30f, -1e30f};
    float li2[2] = {0.f, 0.f};
    float o[8][4];
    #pragma unroll
    for (int ni = 0; ni < 8; ni++)
        #pragma unroll
        for (int j = 0; j < 4; j++) o[ni][j] = 0.f;

    const int ktiles = 2 * qt + 2;
    #pragma unroll 1
    for (int jt = 0; jt < ktiles; jt++) {
        const int kb = jt * 64;
        if (jt + 1 < ktiles) { load_kv(jt + 1); CP_WAIT(1); }
        else                 { CP_WAIT(0); }
        __syncthreads();

        const uint32_t Kb = sb + 32768 + (jt & 1) * 16384;
        const uint32_t Vb = Kb + 8192;

        // ---- S = Q K^T ----
        float s[8][4];
        #pragma unroll
        for (int ni = 0; ni < 8; ni++)
            #pragma unroll
            for (int j = 0; j < 4; j++) s[ni][j] = 0.f;

        #pragma unroll
        for (int ks = 0; ks < 4; ks++) {
            const int kh = ks * 16 + (lane >> 4) * 8;
            uint32_t a0, a1, a2, a3;
            LDSM_X4(a0, a1, a2, a3,
                    Qs + SW128((wrow + (lane & 15)) * 128 + kh * 2));
            #pragma unroll
            for (int np = 0; np < 4; np++) {
                uint32_t r0, r1, r2, r3;
                LDSM_X4(r0, r1, r2, r3,
                        Kb + SW128((np * 16 + (lane & 15)) * 128 + kh * 2));
                mma_f16(s[2 * np],     a0, a1, a2, a3, r0, r2);
                mma_f16(s[2 * np + 1], a0, a1, a2, a3, r1, r3);
            }
        }

        // Causal mask
        if (kb + 63 > qbase + wrow) {
            #pragma unroll
            for (int ni = 0; ni < 8; ni++)
                #pragma unroll
                for (int j = 0; j < 4; j++) {
                    int col = kb + ni * 8 + 2 * lr + (j & 1);
                    int row = qbase + wrow + lq + ((j >> 1) << 3);
                    if (col > row) s[ni][j] = -1e30f;
                }
        }

        // Online softmax (2 rows/thread; quad reduce over lr)
        #pragma unroll
        for (int rr = 0; rr < 2; rr++) {
            float mx = -1e30f;
            #pragma unroll
            for (int ni = 0; ni < 8; ni++)
                mx = fmaxf(mx, fmaxf(s[ni][rr * 2], s[ni][rr * 2 + 1]));
            mx = fmaxf(mx, __shfl_xor_sync(0xffffffffu, mx, 1));
            mx = fmaxf(mx, __shfl_xor_sync(0xffffffffu, mx, 2));
            float mn = fmaxf(mi2[rr], mx);
            float alpha = __expf(mi2[rr] - mn);
            float sum = 0.f;
            #pragma unroll
            for (int ni = 0; ni < 8; ni++) {
                s[ni][rr * 2]     = __expf(s[ni][rr * 2]     - mn);
                s[ni][rr * 2 + 1] = __expf(s[ni][rr * 2 + 1] - mn);
                sum += s[ni][rr * 2] + s[ni][rr * 2 + 1];
            }
            sum += __shfl_xor_sync(0xffffffffu, sum, 1);
            sum += __shfl_xor_sync(0xffffffffu, sum, 2);
            li2[rr] = li2[rr] * alpha + sum;
            mi2[rr] = mn;
            #pragma unroll
            for (int ni = 0; ni < 8; ni++) {
                o[ni][rr * 2]     *= alpha;
                o[ni][rr * 2 + 1] *= alpha;
            }
        }

        // P -> smem (own warp's rows only)
        #pragma unroll
        for (int rr = 0; rr < 2; rr++) {
            int r = wrow + lq + rr * 8;
            #pragma unroll
            for (int ni = 0; ni < 8; ni++) {
                __half2 hv = __floats2half2_rn(s[ni][rr * 2], s[ni][rr * 2 + 1]);
                *(__half2*)((char*)dsm + (Ps - raw) + SW128(r * 128 + (ni * 8 + 2 * lr) * 2)) = hv;
            }
        }
        __syncwarp();

        // ---- O += P V ----  (V [kv][d] in smem; trans-ldmatrix -> B frags)
        #pragma unroll
        for (int ks = 0; ks < 4; ks++) {
            const int kh = ks * 16 + (lane >> 4) * 8;
            uint32_t a0, a1, a2, a3;
            LDSM_X4(a0, a1, a2, a3,
                    Ps + SW128((wrow + (lane & 15)) * 128 + kh * 2));
            #pragma unroll
            for (int dt = 0; dt < 4; dt++) {
                // lanes 0-7: kv lo / d lo ; 8-15: kv hi / d lo ; 16-23: kv lo / d hi ; 24-31: kv hi / d hi
                int kvr = ks * 16 + ((lane >> 3) & 1) * 8 + (lane & 7);
                int dof = dt * 16 + (lane >> 4) * 8;
                uint32_t r0, r1, r2, r3;
                LDSM_X4_T(r0, r1, r2, r3, Vb + SW128(kvr * 128 + dof * 2));
                mma_f16(o[dt * 2],     a0, a1, a2, a3, r0, r1);
                mma_f16(o[dt * 2 + 1], a0, a1, a2, a3, r2, r3);
            }
        }
        __syncthreads();
    }

    // Epilogue: g_heads[b][row][h*64+d] fp32
    const int b = bh >> 3, h = bh & 7;
    #pragma unroll
    for (int rr = 0; rr < 2; rr++) {
        float inv = 1.f / li2[rr];
        int row = qbase + wrow + lq + rr * 8;
        #pragma unroll
        for (int ni = 0; ni < 8; ni++) {
            size_t off = ((size_t)b * PS + row) * PD + h * HD + ni * 8 + 2 * lr;
            *(float2*)(g_heads + off) =
                make_float2(o[ni][rr * 2] * inv, o[ni][rr * 2 + 1] * inv);
        }
    }
}

// ---------------------------------------------------------------------------
// Cross-head normalization (fp32 math) -> fp16 for the final GEMM
// ---------------------------------------------------------------------------
__global__ void __launch_bounds__(256)
norm_k(const float* __restrict__ head_mults)
{
    int i = blockIdx.x * blockDim.x + threadIdx.x;
    if (i >= PB * PS * HD) return;
    int hd = i & 63;
    int bs = i >> 6;
    size_t base = (size_t)bs * PD + hd;

    float v[PH];
    float mean = 0.f;
    #pragma unroll
    for (int h = 0; h < PH; h++) {
        v[h] = g_heads[base + h * HD];
        mean += v[h];
    }
    mean *= (1.f / PH);
    float var = 0.f;
    #pragma unroll
    for (int h = 0; h < PH; h++) {
        float d = v[h] - mean;
        var += d * d;
    }
    var *= (1.f / PH);
    float inv = 1.f / (sqrtf(var) + 0.01f);
    #pragma unroll
    for (int h = 0; h < PH; h++)
        g_normh[base + h * HD] = __float2half((v[h] - mean) * inv * head_mults[h]);
}

// ---------------------------------------------------------------------------
// kernel_launch
// ---------------------------------------------------------------------------
extern "C" void kernel_launch(void* const* d_in, const int* in_sizes, int n_in,
                              void* d_out, int out_size)
{
    const float* query      = (const float*)d_in[0];
    const float* value      = (const float*)d_in[1];
    // d_in[2] = mask: pure causal additive mask, implemented analytically
    const float* Wq         = (const float*)d_in[3];
    const float* Wkv        = (const float*)d_in[4];
    const float* Wo         = (const float*)d_in[5];
    const float* normalizer = (const float*)d_in[6];
    const float* head_mults = (const float*)d_in[7];
    float* out = (float*)d_out;

    const int SM_BYTES = 65536 + 1024;
    cudaFuncSetAttribute(gemm_h<0>, cudaFuncAttributeMaxDynamicSharedMemorySize, SM_BYTES);
    cudaFuncSetAttribute(gemm_h<1>, cudaFuncAttributeMaxDynamicSharedMemorySize, SM_BYTES);
    cudaFuncSetAttribute(flash_h,   cudaFuncAttributeMaxDynamicSharedMemorySize, SM_BYTES);

    __half *qin, *vin, *wT, *woT, *normh;
    cudaGetSymbolAddress((void**)&qin,   g_qin);
    cudaGetSymbolAddress((void**)&vin,   g_vin);
    cudaGetSymbolAddress((void**)&wT,    g_wT);
    cudaGetSymbolAddress((void**)&woT,   g_woT);
    cudaGetSymbolAddress((void**)&normh, g_normh);

    // 0. Convert activations & weights to fp16 (the single mma-input rounding)
    a2h<<<PM * PD / (256 * 4), 256>>>(query, qin);
    a2h<<<PM * PD / (256 * 4), 256>>>(value, vin);
    wtrans<<<dim3(PD / 32, PD / 32), 256>>>(Wq, wT, PD, PD);                   // rows 0-511: Wq^T
    wtrans<<<dim3(2 * PD / 32, PD / 32), 256>>>(Wkv, wT + PD * PD, PD, 2 * PD); // rows 512-1535: Wk^T,Wv^T
    wtrans<<<dim3(PD / 32, PD / 32), 256>>>(Wo, woT, PD, PD);

    // 1. Fused QKV projection -> g_q (scaled), g_k, g_v  (all [bh][s][d] fp16)
    gemm_h<0><<<dim3(12, PM / 128), 256, SM_BYTES>>>(qin, vin, wT, nullptr, normalizer);

    // 2. Causal flash attention -> g_heads (fp32)
    flash_h<<<dim3(PS / 128, BH), 256, SM_BYTES>>>();

    // 3. Cross-head normalization -> g_normh (fp16)
    norm_k<<<(PB * PS * HD + 255) / 256, 256>>>(head_mults);

    // 4. Output projection -> d_out (fp32)
    gemm_h<1><<<dim3(4, PM / 128), 256, SM_BYTES>>>(normh, nullptr, woT, out, nullptr);
}

// round 5
// speedup vs baseline: 5.8827x; 1.0669x over previous
#include <cuda_runtime.h>
#include <cuda_fp16.h>
#include <cstdint>

// Problem constants
#define PB 4
#define PS 2048
#define PD 512
#define PH 8
#define HD 64
#define BH (PB*PH)          // 32
#define PM (PB*PS)          // 8192

// Scratch (device globals; no allocations allowed)
__device__ __half g_qin[PM * PD];        // query in fp16
__device__ __half g_vin[PM * PD];        // value in fp16
__device__ __half g_wT[3 * PD * PD];     // [Wq^T | Wk^T | Wv^T] fp16, [n][k]
__device__ __half g_woT[PD * PD];        // Wo^T fp16 [n][k]
__device__ __half g_q[BH * PS * HD];     // [bh][s][d] fp16, pre-scaled by normalizer*log2e
__device__ __half g_k[BH * PS * HD];     // [bh][s][d] fp16
__device__ __half g_v[BH * PS * HD];     // [bh][s][d] fp16
__device__ float  g_heads[PB * PS * PD]; // [b][s][h*64+hd] fp32
__device__ __half g_normh[PM * PD];      // normalized heads fp16

// ---------------------------------------------------------------------------
// helpers
// ---------------------------------------------------------------------------
__device__ __forceinline__ uint32_t smem_u32(const void* p) {
    uint32_t a;
    asm("{ .reg .u64 t; cvta.to.shared.u64 t, %1; cvt.u32.u64 %0, t; }"
        : "=r"(a) : "l"(p));
    return a;
}

__device__ __forceinline__ float fexp2(float x) {
    float y;
    asm("ex2.approx.f32 %0, %1;" : "=f"(y) : "f"(x));
    return y;
}

#define SW128(off) ((off) ^ (((off) >> 3) & 0x70))

#define CP16(dst, src) \
    asm volatile("cp.async.cg.shared.global [%0], [%1], 16;" \
                 :: "r"((uint32_t)(dst)), "l"(src))
#define CP_COMMIT() asm volatile("cp.async.commit_group;" ::: "memory")
#define CP_WAIT(n)  asm volatile("cp.async.wait_group %0;" :: "n"(n) : "memory")

#define LDSM_X4(r0, r1, r2, r3, addr) \
    asm volatile("ldmatrix.sync.aligned.m8n8.x4.shared.b16 {%0,%1,%2,%3}, [%4];" \
                 : "=r"(r0), "=r"(r1), "=r"(r2), "=r"(r3) : "r"(addr))
#define LDSM_X4_T(r0, r1, r2, r3, addr) \
    asm volatile("ldmatrix.sync.aligned.m8n8.x4.trans.shared.b16 {%0,%1,%2,%3}, [%4];" \
                 : "=r"(r0), "=r"(r1), "=r"(r2), "=r"(r3) : "r"(addr))

__device__ __forceinline__ void mma_f16(float c[4], uint32_t a0, uint32_t a1,
                                        uint32_t a2, uint32_t a3,
                                        uint32_t b0, uint32_t b1) {
    asm volatile(
        "mma.sync.aligned.m16n8k16.row.col.f32.f16.f16.f32 "
        "{%0,%1,%2,%3}, {%4,%5,%6,%7}, {%8,%9}, {%0,%1,%2,%3};\n"
        : "+f"(c[0]), "+f"(c[1]), "+f"(c[2]), "+f"(c[3])
        : "r"(a0), "r"(a1), "r"(a2), "r"(a3), "r"(b0), "r"(b1));
}

// ---------------------------------------------------------------------------
// Fused prep: blocks 0-4095 convert query, 4096-8191 convert value,
// 8192-9215 transpose Wq/Wkv/Wo to fp16 K-major.
// ---------------------------------------------------------------------------
__global__ void __launch_bounds__(256)
prep(const float* __restrict__ query, const float* __restrict__ value,
     const float* __restrict__ Wq, const float* __restrict__ Wkv,
     const float* __restrict__ Wo)
{
    const int bx = blockIdx.x;
    if (bx < 8192) {
        const float* src = (bx < 4096) ? query : value;
        __half* dst = (bx < 4096) ? g_qin : g_vin;
        size_t off = (size_t)(bx & 4095) * 1024 + threadIdx.x * 4;
        float4 v = *(const float4*)(src + off);
        __half2 h0 = __floats2half2_rn(v.x, v.y);
        __half2 h1 = __floats2half2_rn(v.z, v.w);
        *(uint2*)(dst + off) = make_uint2(*(uint32_t*)&h0, *(uint32_t*)&h1);
        return;
    }
    // transpose: out[n][k] = h(in[k][n])
    __shared__ float t[32][33];
    int tt = bx - 8192;
    const float* src; __half* dst; int Nd, bn, bk;
    if (tt < 256)      { src = Wq;  dst = g_wT;             Nd = 512;  bn = (tt & 15) * 32; bk = (tt >> 4) * 32; }
    else if (tt < 768) { int u = tt - 256;
                         src = Wkv; dst = g_wT + PD * PD;   Nd = 1024; bn = (u & 31) * 32;  bk = (u >> 5) * 32; }
    else               { int u = tt - 768;
                         src = Wo;  dst = g_woT;            Nd = 512;  bn = (u & 15) * 32;  bk = (u >> 4) * 32; }
    int tx = threadIdx.x & 31, ty = threadIdx.x >> 5;
    #pragma unroll
    for (int j = 0; j < 32; j += 8)
        t[ty + j][tx] = src[(size_t)(bk + ty + j) * Nd + bn + tx];
    __syncthreads();
    #pragma unroll
    for (int j = 0; j < 32; j += 8)
        dst[(size_t)(bn + ty + j) * PD + bk + tx] = __float2half(t[tx][ty + j]);
}

// ---------------------------------------------------------------------------
// fp16 GEMM: 128x128 CTA tile, K=512 in 8 chunks of 64, cp.async double
// buffered, ldmatrix fragments, m16n8k16 f32-accumulate.
// MODE 0: fused QKV projection (bx: 0-3 Q, 4-7 K, 8-11 V)
// MODE 1: output projection -> fp32 C
// ---------------------------------------------------------------------------
template<int MODE>
__global__ void __launch_bounds__(256, 2)
gemm_h(const __half* __restrict__ Aq, const __half* __restrict__ Av,
       const __half* __restrict__ W, float* __restrict__ C,
       const float* __restrict__ normPtr)
{
    extern __shared__ char dsm[];
    uint32_t raw = smem_u32(dsm);
    uint32_t sb = (raw + 1023u) & ~1023u;

    const int tid = threadIdx.x, warp = tid >> 5, lane = tid & 31;
    const int wm = warp & 3, wn = warp >> 2;
    const int lq = lane >> 2, lr = lane & 3;
    const int bx = blockIdx.x;
    const int m0 = blockIdx.y * 128;
    const int n0 = bx * 128;
    const int sector = (MODE == 0) ? (bx >> 2) : 0;

    const __half* A = (MODE == 0) ? ((sector == 0) ? Aq : Av) : Aq;

    float acc[2][8][4];
    #pragma unroll
    for (int mi = 0; mi < 2; mi++)
        #pragma unroll
        for (int ni = 0; ni < 8; ni++)
            #pragma unroll
            for (int j = 0; j < 4; j++) acc[mi][ni][j] = 0.f;

    auto load_chunk = [&](int i) {
        const int k0 = i * 64;
        const uint32_t dA = sb + (i & 1) * 32768;
        const uint32_t dB = dA + 16384;
        #pragma unroll
        for (int l = 0; l < 4; l++) {
            int idx = tid + l * 256;
            int r = idx >> 3, c = (idx & 7) * 8;
            CP16(dA + SW128(r * 128 + c * 2), A + (size_t)(m0 + r) * PD + k0 + c);
            CP16(dB + SW128(r * 128 + c * 2), W + (size_t)(n0 + r) * PD + k0 + c);
        }
        CP_COMMIT();
    };

    load_chunk(0);

    #pragma unroll 1
    for (int i = 0; i < 8; i++) {
        if (i + 1 < 8) { load_chunk(i + 1); CP_WAIT(1); }
        else           { CP_WAIT(0); }
        __syncthreads();

        const uint32_t Ab = sb + (i & 1) * 32768;
        const uint32_t Bb = Ab + 16384;
        #pragma unroll
        for (int ks = 0; ks < 4; ks++) {
            const int kh = ks * 16 + (lane >> 4) * 8;
            uint32_t a[2][4];
            #pragma unroll
            for (int mi = 0; mi < 2; mi++) {
                int row = wm * 32 + mi * 16 + (lane & 15);
                LDSM_X4(a[mi][0], a[mi][1], a[mi][2], a[mi][3],
                        Ab + SW128(row * 128 + kh * 2));
            }
            #pragma unroll
            for (int np = 0; np < 4; np++) {
                uint32_t r0, r1, r2, r3;
                int row = wn * 64 + np * 16 + (lane & 15);
                LDSM_X4(r0, r1, r2, r3, Bb + SW128(row * 128 + kh * 2));
                #pragma unroll
                for (int mi = 0; mi < 2; mi++) {
                    mma_f16(acc[mi][2 * np],     a[mi][0], a[mi][1], a[mi][2], a[mi][3], r0, r2);
                    mma_f16(acc[mi][2 * np + 1], a[mi][0], a[mi][1], a[mi][2], a[mi][3], r1, r3);
                }
            }
        }
        __syncthreads();
    }

    if (MODE == 1) {
        #pragma unroll
        for (int mi = 0; mi < 2; mi++)
            #pragma unroll
            for (int rr = 0; rr < 2; rr++) {
                int m = m0 + wm * 32 + mi * 16 + lq + rr * 8;
                #pragma unroll
                for (int ni = 0; ni < 8; ni++) {
                    int c = n0 + wn * 64 + ni * 8 + 2 * lr;
                    *(float2*)(C + (size_t)m * PD + c) =
                        make_float2(acc[mi][ni][rr * 2], acc[mi][ni][rr * 2 + 1]);
                }
            }
    } else {
        // Q gets normalizer * log2(e) so flash can use exp2 directly
        const float scale = (sector == 0) ? (*normPtr * 1.4426950408889634f) : 1.f;
        __half* dst = (sector == 0) ? g_q : ((sector == 1) ? g_k : g_v);
        #pragma unroll
        for (int mi = 0; mi < 2; mi++)
            #pragma unroll
            for (int rr = 0; rr < 2; rr++) {
                int m = m0 + wm * 32 + mi * 16 + lq + rr * 8;
                int b = m >> 11, s = m & 2047;
                #pragma unroll
                for (int ni = 0; ni < 8; ni++) {
                    int nn = (bx & 3) * 128 + wn * 64 + ni * 8 + 2 * lr;
                    int h = nn >> 6, d = nn & 63;
                    __half2 hv = __floats2half2_rn(acc[mi][ni][rr * 2] * scale,
                                                   acc[mi][ni][rr * 2 + 1] * scale);
                    *(__half2*)(dst + (((size_t)(b * PH + h)) * PS + s) * HD + d) = hv;
                }
            }
    }
}

// ---------------------------------------------------------------------------
// fp16 flash attention: 128 q-rows x 64 kv per step, 8 warps (16 rows each).
// Q fragments register-resident; P kept in registers (S C-frag == PV A-frag).
// exp2-domain softmax (Q pre-scaled by normalizer*log2e). Causal.
// ---------------------------------------------------------------------------
__global__ void __launch_bounds__(256, 2)
flash_h()
{
    extern __shared__ char dsm[];
    uint32_t raw = smem_u32(dsm);
    uint32_t sb = (raw + 1023u) & ~1023u;
    const uint32_t Qs = sb;  // 16KB [r][d]
    // KV buffers: buf b at sb+16384+b*16384 (K 8KB, V 8KB)

    const int bh = blockIdx.y;
    const int qt = (int)gridDim.x - 1 - (int)blockIdx.x;  // heavy first
    const int qbase = qt * 128;

    const int tid = threadIdx.x, warp = tid >> 5, lane = tid & 31;
    const int lq = lane >> 2, lr = lane & 3;
    const int wrow = warp * 16;

    const __half* qp = g_q + (size_t)bh * PS * HD;
    const __half* kp = g_k + (size_t)bh * PS * HD;
    const __half* vp = g_v + (size_t)bh * PS * HD;

    auto load_kv = [&](int jt) {
        const int kb = jt * 64;
        const uint32_t Kb = sb + 16384 + (jt & 1) * 16384;
        const uint32_t Vb = Kb + 8192;
        #pragma unroll
        for (int l = 0; l < 2; l++) {
            int idx = tid + l * 256;
            int r = idx >> 3, c = (idx & 7) * 8;
            CP16(Kb + SW128(r * 128 + c * 2), kp + (size_t)(kb + r) * HD + c);
            CP16(Vb + SW128(r * 128 + c * 2), vp + (size_t)(kb + r) * HD + c);
        }
        CP_COMMIT();
    };

    // Q tile + KV0 (one group)
    #pragma unroll
    for (int l = 0; l < 4; l++) {
        int idx = tid + l * 256;
        int r = idx >> 3, c = (idx & 7) * 8;
        CP16(Qs + SW128(r * 128 + c * 2), qp + (size_t)(qbase + r) * HD + c);
    }
    load_kv(0);
    CP_WAIT(0);
    __syncthreads();

    // Hoist Q fragments (warp-invariant across kv tiles): 16 regs
    uint32_t qf[4][4];
    #pragma unroll
    for (int ks = 0; ks < 4; ks++) {
        const int kh = ks * 16 + (lane >> 4) * 8;
        LDSM_X4(qf[ks][0], qf[ks][1], qf[ks][2], qf[ks][3],
                Qs + SW128((wrow + (lane & 15)) * 128 + kh * 2));
    }

    float mi2[2] = {-1e30f, -1e30f};
    float li2[2] = {0.f, 0.f};
    float o[8][4];
    #pragma unroll
    for (int ni = 0; ni < 8; ni++)
        #pragma unroll
        for (int j = 0; j < 4; j++) o[ni][j] = 0.f;

    const int ktiles = 2 * qt + 2;
    #pragma unroll 1
    for (int jt = 0; jt < ktiles; jt++) {
        const int kb = jt * 64;
        if (jt + 1 < ktiles) { load_kv(jt + 1); CP_WAIT(1); }
        else                 { CP_WAIT(0); }
        __syncthreads();

        // Skip warp-tiles entirely above the diagonal
        if (kb <= qbase + wrow + 15) {
            const uint32_t Kb = sb + 16384 + (jt & 1) * 16384;
            const uint32_t Vb = Kb + 8192;

            // ---- S = Q K^T ----
            float s[8][4];
            #pragma unroll
            for (int ni = 0; ni < 8; ni++)
                #pragma unroll
                for (int j = 0; j < 4; j++) s[ni][j] = 0.f;

            #pragma unroll
            for (int ks = 0; ks < 4; ks++) {
                const int kh = ks * 16 + (lane >> 4) * 8;
                #pragma unroll
                for (int np = 0; np < 4; np++) {
                    uint32_t r0, r1, r2, r3;
                    LDSM_X4(r0, r1, r2, r3,
                            Kb + SW128((np * 16 + (lane & 15)) * 128 + kh * 2));
                    mma_f16(s[2 * np],     qf[ks][0], qf[ks][1], qf[ks][2], qf[ks][3], r0, r2);
                    mma_f16(s[2 * np + 1], qf[ks][0], qf[ks][1], qf[ks][2], qf[ks][3], r1, r3);
                }
            }

            // Causal mask (only near the diagonal)
            if (kb + 63 > qbase + wrow) {
                #pragma unroll
                for (int ni = 0; ni < 8; ni++)
                    #pragma unroll
                    for (int j = 0; j < 4; j++) {
                        int col = kb + ni * 8 + 2 * lr + (j & 1);
                        int row = qbase + wrow + lq + ((j >> 1) << 3);
                        if (col > row) s[ni][j] = -1e30f;
                    }
            }

            // Online softmax in exp2 domain (2 rows/thread; quad reduce)
            #pragma unroll
            for (int rr = 0; rr < 2; rr++) {
                float mx = -1e30f;
                #pragma unroll
                for (int ni = 0; ni < 8; ni++)
                    mx = fmaxf(mx, fmaxf(s[ni][rr * 2], s[ni][rr * 2 + 1]));
                mx = fmaxf(mx, __shfl_xor_sync(0xffffffffu, mx, 1));
                mx = fmaxf(mx, __shfl_xor_sync(0xffffffffu, mx, 2));
                float mn = fmaxf(mi2[rr], mx);
                float alpha = fexp2(mi2[rr] - mn);
                float sum = 0.f;
                #pragma unroll
                for (int ni = 0; ni < 8; ni++) {
                    s[ni][rr * 2]     = fexp2(s[ni][rr * 2]     - mn);
                    s[ni][rr * 2 + 1] = fexp2(s[ni][rr * 2 + 1] - mn);
                    sum += s[ni][rr * 2] + s[ni][rr * 2 + 1];
                }
                sum += __shfl_xor_sync(0xffffffffu, sum, 1);
                sum += __shfl_xor_sync(0xffffffffu, sum, 2);
                li2[rr] = li2[rr] * alpha + sum;
                mi2[rr] = mn;
                #pragma unroll
                for (int ni = 0; ni < 8; ni++) {
                    o[ni][rr * 2]     *= alpha;
                    o[ni][rr * 2 + 1] *= alpha;
                }
            }

            // P fragments directly from S accumulators (no smem round-trip):
            // a-frag for kv-chunk ks = {ph[2ks][0], ph[2ks][1], ph[2ks+1][0], ph[2ks+1][1]}
            uint32_t ph[8][2];
            #pragma unroll
            for (int ni = 0; ni < 8; ni++) {
                __half2 h0 = __floats2half2_rn(s[ni][0], s[ni][1]);
                __half2 h1 = __floats2half2_rn(s[ni][2], s[ni][3]);
                ph[ni][0] = *(uint32_t*)&h0;
                ph[ni][1] = *(uint32_t*)&h1;
            }

            // ---- O += P V ----  (V [kv][d] in smem; trans-ldmatrix B frags)
            #pragma unroll
            for (int ks = 0; ks < 4; ks++) {
                #pragma unroll
                for (int dt = 0; dt < 4; dt++) {
                    int kvr = ks * 16 + ((lane >> 3) & 1) * 8 + (lane & 7);
                    int dof = dt * 16 + (lane >> 4) * 8;
                    uint32_t r0, r1, r2, r3;
                    LDSM_X4_T(r0, r1, r2, r3, Vb + SW128(kvr * 128 + dof * 2));
                    mma_f16(o[dt * 2],     ph[2 * ks][0], ph[2 * ks][1],
                            ph[2 * ks + 1][0], ph[2 * ks + 1][1], r0, r1);
                    mma_f16(o[dt * 2 + 1], ph[2 * ks][0], ph[2 * ks][1],
                            ph[2 * ks + 1][0], ph[2 * ks + 1][1], r2, r3);
                }
            }
        }
        __syncthreads();
    }

    // Epilogue: g_heads[b][row][h*64+d] fp32
    const int b = bh >> 3, h = bh & 7;
    #pragma unroll
    for (int rr = 0; rr < 2; rr++) {
        float inv = 1.f / li2[rr];
        int row = qbase + wrow + lq + rr * 8;
        #pragma unroll
        for (int ni = 0; ni < 8; ni++) {
            size_t off = ((size_t)b * PS + row) * PD + h * HD + ni * 8 + 2 * lr;
            *(float2*)(g_heads + off) =
                make_float2(o[ni][rr * 2] * inv, o[ni][rr * 2 + 1] * inv);
        }
    }
}

// ---------------------------------------------------------------------------
// Cross-head normalization (fp32 math, float4-vectorized) -> fp16
// ---------------------------------------------------------------------------
__global__ void __launch_bounds__(256)
norm_k(const float* __restrict__ head_mults)
{
    int i = (blockIdx.x * 256 + threadIdx.x) * 4;  // over B*S*64, 4 hd/thread
    int hd = i & 63;
    int bs = i >> 6;
    size_t base = (size_t)bs * PD + hd;

    float4 v[PH];
    float4 mean = make_float4(0.f, 0.f, 0.f, 0.f);
    #pragma unroll
    for (int h = 0; h < PH; h++) {
        v[h] = *(const float4*)(g_heads + base + h * HD);
        mean.x += v[h].x; mean.y += v[h].y; mean.z += v[h].z; mean.w += v[h].w;
    }
    mean.x *= 0.125f; mean.y *= 0.125f; mean.z *= 0.125f; mean.w *= 0.125f;
    float4 var = make_float4(0.f, 0.f, 0.f, 0.f);
    #pragma unroll
    for (int h = 0; h < PH; h++) {
        float dx = v[h].x - mean.x, dy = v[h].y - mean.y;
        float dz = v[h].z - mean.z, dw = v[h].w - mean.w;
        var.x += dx * dx; var.y += dy * dy; var.z += dz * dz; var.w += dw * dw;
    }
    float ix = 1.f / (sqrtf(var.x * 0.125f) + 0.01f);
    float iy = 1.f / (sqrtf(var.y * 0.125f) + 0.01f);
    float iz = 1.f / (sqrtf(var.z * 0.125f) + 0.01f);
    float iw = 1.f / (sqrtf(var.w * 0.125f) + 0.01f);
    #pragma unroll
    for (int h = 0; h < PH; h++) {
        float hm = head_mults[h];
        __half2 h0 = __floats2half2_rn((v[h].x - mean.x) * ix * hm,
                                       (v[h].y - mean.y) * iy * hm);
        __half2 h1 = __floats2half2_rn((v[h].z - mean.z) * iz * hm,
                                       (v[h].w - mean.w) * iw * hm);
        *(uint2*)(g_normh + base + h * HD) = make_uint2(*(uint32_t*)&h0, *(uint32_t*)&h1);
    }
}

// ---------------------------------------------------------------------------
// kernel_launch
// ---------------------------------------------------------------------------
extern "C" void kernel_launch(void* const* d_in, const int* in_sizes, int n_in,
                              void* d_out, int out_size)
{
    const float* query      = (const float*)d_in[0];
    const float* value      = (const float*)d_in[1];
    // d_in[2] = mask: pure causal additive mask, implemented analytically
    const float* Wq         = (const float*)d_in[3];
    const float* Wkv        = (const float*)d_in[4];
    const float* Wo         = (const float*)d_in[5];
    const float* normalizer = (const float*)d_in[6];
    const float* head_mults = (const float*)d_in[7];
    float* out = (float*)d_out;

    const int GEMM_SMEM  = 65536 + 1024;
    const int FLASH_SMEM = 49152 + 1024;
    cudaFuncSetAttribute(gemm_h<0>, cudaFuncAttributeMaxDynamicSharedMemorySize, GEMM_SMEM);
    cudaFuncSetAttribute(gemm_h<1>, cudaFuncAttributeMaxDynamicSharedMemorySize, GEMM_SMEM);
    cudaFuncSetAttribute(flash_h,   cudaFuncAttributeMaxDynamicSharedMemorySize, FLASH_SMEM);

    __half *qin, *vin, *wT, *woT, *normh;
    cudaGetSymbolAddress((void**)&qin,   g_qin);
    cudaGetSymbolAddress((void**)&vin,   g_vin);
    cudaGetSymbolAddress((void**)&wT,    g_wT);
    cudaGetSymbolAddress((void**)&woT,   g_woT);
    cudaGetSymbolAddress((void**)&normh, g_normh);

    // 0. Fused prep: fp16 conversion of activations + weight transposes
    prep<<<8192 + 1024, 256>>>(query, value, Wq, Wkv, Wo);

    // 1. Fused QKV projection -> g_q (scaled by normalizer*log2e), g_k, g_v
    gemm_h<0><<<dim3(12, PM / 128), 256, GEMM_SMEM>>>(qin, vin, wT, nullptr, normalizer);

    // 2. Causal flash attention -> g_heads (fp32)
    flash_h<<<dim3(PS / 128, BH), 256, FLASH_SMEM>>>();

    // 3. Cross-head normalization -> g_normh (fp16)
    norm_k<<<PB * PS * HD / 1024, 256>>>(head_mults);

    // 4. Output projection -> d_out (fp32)
    gemm_h<1><<<dim3(4, PM / 128), 256, GEMM_SMEM>>>(normh, nullptr, woT, out, nullptr);
}

// round 6
// speedup vs baseline: 6.4137x; 1.0903x over previous
#include <cuda_runtime.h>
#include <cuda_fp16.h>
#include <cstdint>

// Problem constants
#define PB 4
#define PS 2048
#define PD 512
#define PH 8
#define HD 64
#define BH (PB*PH)          // 32
#define PM (PB*PS)          // 8192

// Scratch (device globals; no allocations allowed)
__device__ __half g_qin[PM * PD];        // query in fp16
__device__ __half g_vin[PM * PD];        // value in fp16
__device__ __half g_wT[3 * PD * PD];     // [Wq^T | Wk^T | Wv^T] fp16, [n][k]
__device__ __half g_woT[PD * PD];        // Wo^T fp16 [n][k]
__device__ __half g_q[BH * PS * HD];     // [bh][s][d] fp16, pre-scaled by normalizer*log2e
__device__ __half g_k[BH * PS * HD];     // [bh][s][d] fp16
__device__ __half g_v[BH * PS * HD];     // [bh][s][d] fp16
__device__ float  g_heads[PB * PS * PD]; // [b][s][h*64+hd] fp32
__device__ __half g_normh[PM * PD];      // normalized heads fp16

// ---------------------------------------------------------------------------
// helpers
// ---------------------------------------------------------------------------
__device__ __forceinline__ uint32_t smem_u32(const void* p) {
    uint32_t a;
    asm("{ .reg .u64 t; cvta.to.shared.u64 t, %1; cvt.u32.u64 %0, t; }"
        : "=r"(a) : "l"(p));
    return a;
}

__device__ __forceinline__ float fexp2(float x) {
    float y;
    asm("ex2.approx.f32 %0, %1;" : "=f"(y) : "f"(x));
    return y;
}

__device__ __forceinline__ uint32_t hexp2(uint32_t x) {
    uint32_t y;
    asm("ex2.approx.f16x2 %0, %1;" : "=r"(y) : "r"(x));
    return y;
}

#define SW128(off) ((off) ^ (((off) >> 3) & 0x70))

#define CP16(dst, src) \
    asm volatile("cp.async.cg.shared.global [%0], [%1], 16;" \
                 :: "r"((uint32_t)(dst)), "l"(src))
#define CP_COMMIT() asm volatile("cp.async.commit_group;" ::: "memory")
#define CP_WAIT(n)  asm volatile("cp.async.wait_group %0;" :: "n"(n) : "memory")

#define LDSM_X4(r0, r1, r2, r3, addr) \
    asm volatile("ldmatrix.sync.aligned.m8n8.x4.shared.b16 {%0,%1,%2,%3}, [%4];" \
                 : "=r"(r0), "=r"(r1), "=r"(r2), "=r"(r3) : "r"(addr))
#define LDSM_X4_T(r0, r1, r2, r3, addr) \
    asm volatile("ldmatrix.sync.aligned.m8n8.x4.trans.shared.b16 {%0,%1,%2,%3}, [%4];" \
                 : "=r"(r0), "=r"(r1), "=r"(r2), "=r"(r3) : "r"(addr))

__device__ __forceinline__ void mma_f16(float c[4], uint32_t a0, uint32_t a1,
                                        uint32_t a2, uint32_t a3,
                                        uint32_t b0, uint32_t b1) {
    asm volatile(
        "mma.sync.aligned.m16n8k16.row.col.f32.f16.f16.f32 "
        "{%0,%1,%2,%3}, {%4,%5,%6,%7}, {%8,%9}, {%0,%1,%2,%3};\n"
        : "+f"(c[0]), "+f"(c[1]), "+f"(c[2]), "+f"(c[3])
        : "r"(a0), "r"(a1), "r"(a2), "r"(a3), "r"(b0), "r"(b1));
}

// ---------------------------------------------------------------------------
// Fused prep: blocks 0-8191 convert query/value to fp16; 8192+ transpose
// weights to fp16 K-major.
// ---------------------------------------------------------------------------
__global__ void __launch_bounds__(256)
prep(const float* __restrict__ query, const float* __restrict__ value,
     const float* __restrict__ Wq, const float* __restrict__ Wkv,
     const float* __restrict__ Wo)
{
    const int bx = blockIdx.x;
    if (bx < 8192) {
        const float* src = (bx < 4096) ? query : value;
        __half* dst = (bx < 4096) ? g_qin : g_vin;
        size_t off = (size_t)(bx & 4095) * 1024 + threadIdx.x * 4;
        float4 v = *(const float4*)(src + off);
        __half2 h0 = __floats2half2_rn(v.x, v.y);
        __half2 h1 = __floats2half2_rn(v.z, v.w);
        *(uint2*)(dst + off) = make_uint2(*(uint32_t*)&h0, *(uint32_t*)&h1);
        return;
    }
    __shared__ float t[32][33];
    int tt = bx - 8192;
    const float* src; __half* dst; int Nd, bn, bk;
    if (tt < 256)      { src = Wq;  dst = g_wT;           Nd = 512;  bn = (tt & 15) * 32; bk = (tt >> 4) * 32; }
    else if (tt < 768) { int u = tt - 256;
                         src = Wkv; dst = g_wT + PD * PD; Nd = 1024; bn = (u & 31) * 32;  bk = (u >> 5) * 32; }
    else               { int u = tt - 768;
                         src = Wo;  dst = g_woT;          Nd = 512;  bn = (u & 15) * 32;  bk = (u >> 4) * 32; }
    int tx = threadIdx.x & 31, ty = threadIdx.x >> 5;
    #pragma unroll
    for (int j = 0; j < 32; j += 8)
        t[ty + j][tx] = src[(size_t)(bk + ty + j) * Nd + bn + tx];
    __syncthreads();
    #pragma unroll
    for (int j = 0; j < 32; j += 8)
        dst[(size_t)(bn + ty + j) * PD + bk + tx] = __float2half(t[tx][ty + j]);
}

// ---------------------------------------------------------------------------
// fp16 GEMM: 128x128 CTA tile, K=512 in 8 chunks of 64, 3-stage cp.async
// pipeline (single __syncthreads per chunk), ldmatrix + m16n8k16 f32-acc.
// MODE 0: fused QKV projection (bx: 0-3 Q, 4-7 K, 8-11 V)
// MODE 1: output projection -> fp32 C
// ---------------------------------------------------------------------------
template<int MODE>
__global__ void __launch_bounds__(256, 2)
gemm_h(const __half* __restrict__ Aq, const __half* __restrict__ Av,
       const __half* __restrict__ W, float* __restrict__ C,
       const float* __restrict__ normPtr)
{
    extern __shared__ char dsm[];
    uint32_t raw = smem_u32(dsm);
    uint32_t sb = (raw + 1023u) & ~1023u;

    const int tid = threadIdx.x, warp = tid >> 5, lane = tid & 31;
    const int wm = warp & 3, wn = warp >> 2;
    const int lq = lane >> 2, lr = lane & 3;
    const int bx = blockIdx.x;
    const int m0 = blockIdx.y * 128;
    const int n0 = bx * 128;
    const int sector = (MODE == 0) ? (bx >> 2) : 0;

    const __half* A = (MODE == 0) ? ((sector == 0) ? Aq : Av) : Aq;

    float acc[2][8][4];
    #pragma unroll
    for (int mi = 0; mi < 2; mi++)
        #pragma unroll
        for (int ni = 0; ni < 8; ni++)
            #pragma unroll
            for (int j = 0; j < 4; j++) acc[mi][ni][j] = 0.f;

    auto load_chunk = [&](int i) {
        const int k0 = i * 64;
        const uint32_t dA = sb + (i % 3) * 32768;
        const uint32_t dB = dA + 16384;
        #pragma unroll
        for (int l = 0; l < 4; l++) {
            int idx = tid + l * 256;
            int r = idx >> 3, c = (idx & 7) * 8;
            CP16(dA + SW128(r * 128 + c * 2), A + (size_t)(m0 + r) * PD + k0 + c);
            CP16(dB + SW128(r * 128 + c * 2), W + (size_t)(n0 + r) * PD + k0 + c);
        }
        CP_COMMIT();
    };

    load_chunk(0);
    load_chunk(1);

    #pragma unroll 1
    for (int i = 0; i < 8; i++) {
        CP_WAIT(1);
        __syncthreads();
        if (i + 2 < 8) load_chunk(i + 2);  // writes buf (i+2)%3 == (i-1)%3: safe after sync

        const uint32_t Ab = sb + (i % 3) * 32768;
        const uint32_t Bb = Ab + 16384;
        #pragma unroll
        for (int ks = 0; ks < 4; ks++) {
            const int kh = ks * 16 + (lane >> 4) * 8;
            uint32_t a[2][4];
            #pragma unroll
            for (int mi = 0; mi < 2; mi++) {
                int row = wm * 32 + mi * 16 + (lane & 15);
                LDSM_X4(a[mi][0], a[mi][1], a[mi][2], a[mi][3],
                        Ab + SW128(row * 128 + kh * 2));
            }
            #pragma unroll
            for (int np = 0; np < 4; np++) {
                uint32_t r0, r1, r2, r3;
                int row = wn * 64 + np * 16 + (lane & 15);
                LDSM_X4(r0, r1, r2, r3, Bb + SW128(row * 128 + kh * 2));
                #pragma unroll
                for (int mi = 0; mi < 2; mi++) {
                    mma_f16(acc[mi][2 * np],     a[mi][0], a[mi][1], a[mi][2], a[mi][3], r0, r2);
                    mma_f16(acc[mi][2 * np + 1], a[mi][0], a[mi][1], a[mi][2], a[mi][3], r1, r3);
                }
            }
        }
    }

    if (MODE == 1) {
        #pragma unroll
        for (int mi = 0; mi < 2; mi++)
            #pragma unroll
            for (int rr = 0; rr < 2; rr++) {
                int m = m0 + wm * 32 + mi * 16 + lq + rr * 8;
                #pragma unroll
                for (int ni = 0; ni < 8; ni++) {
                    int c = n0 + wn * 64 + ni * 8 + 2 * lr;
                    *(float2*)(C + (size_t)m * PD + c) =
                        make_float2(acc[mi][ni][rr * 2], acc[mi][ni][rr * 2 + 1]);
                }
            }
    } else {
        // Q gets normalizer * log2(e) so flash can use exp2 directly
        const float scale = (sector == 0) ? (*normPtr * 1.4426950408889634f) : 1.f;
        __half* dst = (sector == 0) ? g_q : ((sector == 1) ? g_k : g_v);
        #pragma unroll
        for (int mi = 0; mi < 2; mi++)
            #pragma unroll
            for (int rr = 0; rr < 2; rr++) {
                int m = m0 + wm * 32 + mi * 16 + lq + rr * 8;
                int b = m >> 11, s = m & 2047;
                #pragma unroll
                for (int ni = 0; ni < 8; ni++) {
                    int nn = (bx & 3) * 128 + wn * 64 + ni * 8 + 2 * lr;
                    int h = nn >> 6, d = nn & 63;
                    __half2 hv = __floats2half2_rn(acc[mi][ni][rr * 2] * scale,
                                                   acc[mi][ni][rr * 2 + 1] * scale);
                    *(__half2*)(dst + (((size_t)(b * PH + h)) * PS + s) * HD + d) = hv;
                }
            }
    }
}

// ---------------------------------------------------------------------------
// fp16 flash attention: 128 q-rows x 64 kv per step, 8 warps (16 rows each).
// Q fragments register-resident; P register-fused; li via ones-column MMA;
// exp2 in f16x2; 3-stage KV pipeline, one sync per tile. Causal.
// ---------------------------------------------------------------------------
__global__ void __launch_bounds__(256, 2)
flash_h()
{
    extern __shared__ char dsm[];
    uint32_t raw = smem_u32(dsm);
    uint32_t sb = (raw + 1023u) & ~1023u;
    const uint32_t Qs = sb;  // 16KB [r][d]
    // KV buffers: buf b at sb+16384+b*16384 (K 8KB, V 8KB), b in {0,1,2}

    const int bh = blockIdx.y;
    const int qt = (int)gridDim.x - 1 - (int)blockIdx.x;  // heavy first
    const int qbase = qt * 128;

    const int tid = threadIdx.x, warp = tid >> 5, lane = tid & 31;
    const int lq = lane >> 2, lr = lane & 3;
    const int wrow = warp * 16;

    const __half* qp = g_q + (size_t)bh * PS * HD;
    const __half* kp = g_k + (size_t)bh * PS * HD;
    const __half* vp = g_v + (size_t)bh * PS * HD;

    auto load_kv = [&](int jt) {
        const int kb = jt * 64;
        const uint32_t Kb = sb + 16384 + (jt % 3) * 16384;
        const uint32_t Vb = Kb + 8192;
        #pragma unroll
        for (int l = 0; l < 2; l++) {
            int idx = tid + l * 256;
            int r = idx >> 3, c = (idx & 7) * 8;
            CP16(Kb + SW128(r * 128 + c * 2), kp + (size_t)(kb + r) * HD + c);
            CP16(Vb + SW128(r * 128 + c * 2), vp + (size_t)(kb + r) * HD + c);
        }
        CP_COMMIT();
    };

    const int ktiles = 2 * qt + 2;

    // Q tile in group 0 together with KV0; KV1 in group 1
    #pragma unroll
    for (int l = 0; l < 4; l++) {
        int idx = tid + l * 256;
        int r = idx >> 3, c = (idx & 7) * 8;
        CP16(Qs + SW128(r * 128 + c * 2), qp + (size_t)(qbase + r) * HD + c);
    }
    load_kv(0);
    if (ktiles > 1) load_kv(1);

    CP_WAIT(1);          // group 0 (Q + KV0) done
    __syncthreads();

    // Hoist Q fragments (warp-invariant across kv tiles): 16 regs
    uint32_t qf[4][4];
    #pragma unroll
    for (int ks = 0; ks < 4; ks++) {
        const int kh = ks * 16 + (lane >> 4) * 8;
        LDSM_X4(qf[ks][0], qf[ks][1], qf[ks][2], qf[ks][3],
                Qs + SW128((wrow + (lane & 15)) * 128 + kh * 2));
    }

    const uint32_t ONE2 = 0x3C003C00u;  // half2(1,1)
    float mi2[2] = {-1e30f, -1e30f};
    float lf[4] = {0.f, 0.f, 0.f, 0.f};   // li fragment (cols identical)
    float o[8][4];
    #pragma unroll
    for (int ni = 0; ni < 8; ni++)
        #pragma unroll
        for (int j = 0; j < 4; j++) o[ni][j] = 0.f;

    #pragma unroll 1
    for (int jt = 0; jt < ktiles; jt++) {
        const int kb = jt * 64;
        if (jt > 0) {       // jt==0 already waited above
            CP_WAIT(1);
            __syncthreads();
        }
        if (jt + 2 < ktiles) load_kv(jt + 2);  // buf (jt+2)%3 == (jt-1)%3: safe after sync

        // Skip warp-tiles entirely above the diagonal
        if (kb <= qbase + wrow + 15) {
            const uint32_t Kb = sb + 16384 + (jt % 3) * 16384;
            const uint32_t Vb = Kb + 8192;

            // ---- S = Q K^T ----
            float s[8][4];
            #pragma unroll
            for (int ni = 0; ni < 8; ni++)
                #pragma unroll
                for (int j = 0; j < 4; j++) s[ni][j] = 0.f;

            #pragma unroll
            for (int ks = 0; ks < 4; ks++) {
                const int kh = ks * 16 + (lane >> 4) * 8;
                #pragma unroll
                for (int np = 0; np < 4; np++) {
                    uint32_t r0, r1, r2, r3;
                    LDSM_X4(r0, r1, r2, r3,
                            Kb + SW128((np * 16 + (lane & 15)) * 128 + kh * 2));
                    mma_f16(s[2 * np],     qf[ks][0], qf[ks][1], qf[ks][2], qf[ks][3], r0, r2);
                    mma_f16(s[2 * np + 1], qf[ks][0], qf[ks][1], qf[ks][2], qf[ks][3], r1, r3);
                }
            }

            // Causal mask (only near the diagonal)
            if (kb + 63 > qbase + wrow) {
                #pragma unroll
                for (int ni = 0; ni < 8; ni++)
                    #pragma unroll
                    for (int j = 0; j < 4; j++) {
                        int col = kb + ni * 8 + 2 * lr + (j & 1);
                        int row = qbase + wrow + lq + ((j >> 1) << 3);
                        if (col > row) s[ni][j] = -1e30f;
                    }
            }

            // Row max (fp32, quad reduce) + rescale factors
            float mn[2], alpha[2];
            #pragma unroll
            for (int rr = 0; rr < 2; rr++) {
                float mx = -1e30f;
                #pragma unroll
                for (int ni = 0; ni < 8; ni++)
                    mx = fmaxf(mx, fmaxf(s[ni][rr * 2], s[ni][rr * 2 + 1]));
                mx = fmaxf(mx, __shfl_xor_sync(0xffffffffu, mx, 1));
                mx = fmaxf(mx, __shfl_xor_sync(0xffffffffu, mx, 2));
                mn[rr] = fmaxf(mi2[rr], mx);
                alpha[rr] = fexp2(mi2[rr] - mn[rr]);
                mi2[rr] = mn[rr];
                #pragma unroll
                for (int ni = 0; ni < 8; ni++) {
                    o[ni][rr * 2]     *= alpha[rr];
                    o[ni][rr * 2 + 1] *= alpha[rr];
                }
            }
            lf[0] *= alpha[0]; lf[1] *= alpha[0];
            lf[2] *= alpha[1]; lf[3] *= alpha[1];

            // P = exp2(S - mn) in f16x2; fragments double as PV A-operands
            uint32_t ph[8][2];
            #pragma unroll
            for (int ni = 0; ni < 8; ni++) {
                __half2 h0 = __floats2half2_rn(s[ni][0] - mn[0], s[ni][1] - mn[0]);
                __half2 h1 = __floats2half2_rn(s[ni][2] - mn[1], s[ni][3] - mn[1]);
                ph[ni][0] = hexp2(*(uint32_t*)&h0);
                ph[ni][1] = hexp2(*(uint32_t*)&h1);
            }

            // li += P @ ones  (fp32 accumulate, cross-lane reduce inside mma)
            #pragma unroll
            for (int ks = 0; ks < 4; ks++)
                mma_f16(lf, ph[2 * ks][0], ph[2 * ks][1],
                        ph[2 * ks + 1][0], ph[2 * ks + 1][1], ONE2, ONE2);

            // ---- O += P V ----
            #pragma unroll
            for (int ks = 0; ks < 4; ks++) {
                #pragma unroll
                for (int dt = 0; dt < 4; dt++) {
                    int kvr = ks * 16 + ((lane >> 3) & 1) * 8 + (lane & 7);
                    int dof = dt * 16 + (lane >> 4) * 8;
                    uint32_t r0, r1, r2, r3;
                    LDSM_X4_T(r0, r1, r2, r3, Vb + SW128(kvr * 128 + dof * 2));
                    mma_f16(o[dt * 2],     ph[2 * ks][0], ph[2 * ks][1],
                            ph[2 * ks + 1][0], ph[2 * ks + 1][1], r0, r1);
                    mma_f16(o[dt * 2 + 1], ph[2 * ks][0], ph[2 * ks][1],
                            ph[2 * ks + 1][0], ph[2 * ks + 1][1], r2, r3);
                }
            }
        }
    }

    // Epilogue: g_heads[b][row][h*64+d] fp32
    const int b = bh >> 3, h = bh & 7;
    #pragma unroll
    for (int rr = 0; rr < 2; rr++) {
        float inv = 1.f / lf[rr * 2];
        int row = qbase + wrow + lq + rr * 8;
        #pragma unroll
        for (int ni = 0; ni < 8; ni++) {
            size_t off = ((size_t)b * PS + row) * PD + h * HD + ni * 8 + 2 * lr;
            *(float2*)(g_heads + off) =
                make_float2(o[ni][rr * 2] * inv, o[ni][rr * 2 + 1] * inv);
        }
    }
}

// ---------------------------------------------------------------------------
// Cross-head normalization (fp32 math, float2/thread for latency hiding)
// ---------------------------------------------------------------------------
__global__ void __launch_bounds__(256)
norm_k(const float* __restrict__ head_mults)
{
    int i = (blockIdx.x * 256 + threadIdx.x) * 2;  // over B*S*64, 2 hd/thread
    int hd = i & 63;
    int bs = i >> 6;
    size_t base = (size_t)bs * PD + hd;

    float2 v[PH];
    float2 mean = make_float2(0.f, 0.f);
    #pragma unroll
    for (int h = 0; h < PH; h++) {
        v[h] = *(const float2*)(g_heads + base + h * HD);
        mean.x += v[h].x; mean.y += v[h].y;
    }
    mean.x *= 0.125f; mean.y *= 0.125f;
    float2 var = make_float2(0.f, 0.f);
    #pragma unroll
    for (int h = 0; h < PH; h++) {
        float dx = v[h].x - mean.x, dy = v[h].y - mean.y;
        var.x += dx * dx; var.y += dy * dy;
    }
    float ix = 1.f / (sqrtf(var.x * 0.125f) + 0.01f);
    float iy = 1.f / (sqrtf(var.y * 0.125f) + 0.01f);
    #pragma unroll
    for (int h = 0; h < PH; h++) {
        float hm = head_mults[h];
        __half2 h0 = __floats2half2_rn((v[h].x - mean.x) * ix * hm,
                                       (v[h].y - mean.y) * iy * hm);
        *(uint32_t*)(g_normh + base + h * HD) = *(uint32_t*)&h0;
    }
}

// ---------------------------------------------------------------------------
// kernel_launch
// ---------------------------------------------------------------------------
extern "C" void kernel_launch(void* const* d_in, const int* in_sizes, int n_in,
                              void* d_out, int out_size)
{
    const float* query      = (const float*)d_in[0];
    const float* value      = (const float*)d_in[1];
    // d_in[2] = mask: pure causal additive mask, implemented analytically
    const float* Wq         = (const float*)d_in[3];
    const float* Wkv        = (const float*)d_in[4];
    const float* Wo         = (const float*)d_in[5];
    const float* normalizer = (const float*)d_in[6];
    const float* head_mults = (const float*)d_in[7];
    float* out = (float*)d_out;

    const int GEMM_SMEM  = 3 * 32768 + 1024;   // 99328
    const int FLASH_SMEM = 16384 + 3 * 16384 + 1024;  // 66560
    cudaFuncSetAttribute(gemm_h<0>, cudaFuncAttributeMaxDynamicSharedMemorySize, GEMM_SMEM);
    cudaFuncSetAttribute(gemm_h<1>, cudaFuncAttributeMaxDynamicSharedMemorySize, GEMM_SMEM);
    cudaFuncSetAttribute(flash_h,   cudaFuncAttributeMaxDynamicSharedMemorySize, FLASH_SMEM);

    __half *qin, *vin, *wT, *woT, *normh;
    cudaGetSymbolAddress((void**)&qin,   g_qin);
    cudaGetSymbolAddress((void**)&vin,   g_vin);
    cudaGetSymbolAddress((void**)&wT,    g_wT);
    cudaGetSymbolAddress((void**)&woT,   g_woT);
    cudaGetSymbolAddress((void**)&normh, g_normh);

    // 0. Fused prep: fp16 conversion of activations + weight transposes
    prep<<<8192 + 1024, 256>>>(query, value, Wq, Wkv, Wo);

    // 1. Fused QKV projection -> g_q (scaled by normalizer*log2e), g_k, g_v
    gemm_h<0><<<dim3(12, PM / 128), 256, GEMM_SMEM>>>(qin, vin, wT, nullptr, normalizer);

    // 2. Causal flash attention -> g_heads (fp32)
    flash_h<<<dim3(PS / 128, BH), 256, FLASH_SMEM>>>();

    // 3. Cross-head normalization -> g_normh (fp16)
    norm_k<<<PB * PS * HD / 512, 256>>>(head_mults);

    // 4. Output projection -> d_out (fp32)
    gemm_h<1><<<dim3(4, PM / 128), 256, GEMM_SMEM>>>(normh, nullptr, woT, out, nullptr);
}